// round 5
// baseline (speedup 1.0000x reference)
#include <cuda_runtime.h>
#include <cuda_bf16.h>
#include <math.h>

// TorchLFQ: D=20, K=2^20, TEMP=0.005, tokens = B*N = 256.
// Separable softmax: l_k = A[k>>10] + B[k&1023] (per token).
//
// K1: per-token (256 blocks) compute A[1024], B[1024] in fp64, softmax-normalize
//     each half (pa, pb), per-token entropy H = logZa+logZb - Sa/Za - Sb/Zb,
//     write q = sign(x) and per-token commit partial.
// K2: M[i][j] = sum_t pa[t][i]*pb[t][j]  (1024x1024x256 GEMM, fp32),
//     accumulate sum of (M/256)*log(M/256 + 1e-10) into 512 fixed partials.
// K3: fixed-order reductions -> 4 scalars appended after q in d_out.

#define NTOK   256
#define HT     8          // hi-rows per K2 block
#define TEMP_F 0.005

// Scratch (static device globals; fully rewritten every launch -> deterministic)
__device__ float g_pa[1024 * NTOK];   // layout [hi][token]  (coalesced K2 loads)
__device__ float g_pb[NTOK * 1024];   // layout [token][lo]  (coalesced K2 loads)
__device__ float g_H[NTOK];
__device__ float g_sq[NTOK];
__device__ float g_partials[512];

__global__ void __launch_bounds__(256) lfq_k1(const float* __restrict__ x,
                                              float* __restrict__ qout,
                                              int nTok)
{
    const int t   = blockIdx.x;
    const int tid = threadIdx.x;

    __shared__ double sx[20];
    __shared__ double sred[256];
    __shared__ double sH[1];

    if (tid < 20) sx[tid] = (double)x[t * 20 + tid] / TEMP_F;
    if (tid == 0) sH[0] = 0.0;
    __syncthreads();

    // two halves: hh=0 -> A (dims 0..9, hi bits), hh=1 -> B (dims 10..19, lo bits)
    for (int hh = 0; hh < 2; hh++) {
        double v[4];
        float  e[4];
        double lmax = -1e300;
        #pragma unroll
        for (int r = 0; r < 4; r++) {
            const int h = tid + r * 256;
            double a = 0.0;
            #pragma unroll
            for (int d = 0; d < 10; d++) {
                const double s = sx[hh * 10 + d];
                a += ((h >> (9 - d)) & 1) ? s : -s;
            }
            v[r] = a;
            lmax = fmax(lmax, a);
        }
        // block max
        sred[tid] = lmax; __syncthreads();
        for (int s = 128; s > 0; s >>= 1) {
            if (tid < s) sred[tid] = fmax(sred[tid], sred[tid + s]);
            __syncthreads();
        }
        const double gmax = sred[0];
        __syncthreads();

        double zloc = 0.0, sloc = 0.0;
        #pragma unroll
        for (int r = 0; r < 4; r++) {
            const float am = (float)(v[r] - gmax);   // <= 0
            const float ee = expf(am);
            e[r] = ee;
            zloc += (double)ee;
            sloc += (double)ee * (double)am;
        }
        // block sum Z
        sred[tid] = zloc; __syncthreads();
        for (int s = 128; s > 0; s >>= 1) {
            if (tid < s) sred[tid] += sred[tid + s];
            __syncthreads();
        }
        const double Z = sred[0];
        __syncthreads();
        // block sum S
        sred[tid] = sloc; __syncthreads();
        for (int s = 128; s > 0; s >>= 1) {
            if (tid < s) sred[tid] += sred[tid + s];
            __syncthreads();
        }
        const double S = sred[0];
        __syncthreads();

        const float invZ = (float)(1.0 / Z);
        #pragma unroll
        for (int r = 0; r < 4; r++) {
            const int h = tid + r * 256;
            const float p = e[r] * invZ;
            if (hh == 0) g_pa[h * NTOK + t] = p;
            else         g_pb[t * 1024 + h] = p;
        }
        if (tid == 0) sH[0] += log(Z) - S / Z;
        __syncthreads();
    }

    if (tid == 0) {
        g_H[t] = (float)sH[0];
        double sq = 0.0;
        for (int d = 0; d < 20; d++) {
            const float xv = x[t * 20 + d];
            const float qv = (xv > 0.0f) ? 1.0f : -1.0f;
            qout[t * 20 + d] = qv;
            const double dd = (double)xv - (double)qv;
            sq += dd * dd;
        }
        g_sq[t] = (float)sq;
    }
}

__global__ void __launch_bounds__(256) lfq_k2(int nTok)
{
    const int tid = threadIdx.x;
    const int hi0 = blockIdx.x * HT;
    const int j   = blockIdx.y * 256 + tid;

    __shared__ float spa[NTOK][HT];    // [token][hi-sub]; rows 32B -> float4-able
    #pragma unroll
    for (int h = 0; h < HT; h++)
        spa[tid][h] = g_pa[(hi0 + h) * NTOK + tid];
    __syncthreads();

    float m[HT];
    #pragma unroll
    for (int h = 0; h < HT; h++) m[h] = 0.0f;

    #pragma unroll 4
    for (int t = 0; t < NTOK; t++) {
        const float b = g_pb[t * 1024 + j];
        const float4* pv = reinterpret_cast<const float4*>(&spa[t][0]);
        const float4 p0 = pv[0];
        const float4 p1 = pv[1];
        m[0] += p0.x * b; m[1] += p0.y * b; m[2] += p0.z * b; m[3] += p0.w * b;
        m[4] += p1.x * b; m[5] += p1.y * b; m[6] += p1.z * b; m[7] += p1.w * b;
    }

    const float inv = 1.0f / (float)nTok;
    float local = 0.0f;
    #pragma unroll
    for (int h = 0; h < HT; h++) {
        const float mm = m[h] * inv;
        local += mm * logf(mm + 1e-10f);   // == 0 when mm == 0
    }

    __shared__ float sred[256];
    sred[tid] = local; __syncthreads();
    for (int s = 128; s > 0; s >>= 1) {
        if (tid < s) sred[tid] += sred[tid + s];
        __syncthreads();
    }
    if (tid == 0)
        g_partials[blockIdx.x * gridDim.y + blockIdx.y] = sred[0];
}

__global__ void __launch_bounds__(256) lfq_k3(float* __restrict__ out,
                                              int nTok, int outBase)
{
    const int tid = threadIdx.x;
    __shared__ float sred[256];
    __shared__ float res[3];   // [0]=sum m log m, [1]=Hsum, [2]=sqsum

    // mixture-entropy partials (512 -> 1)
    float v = g_partials[tid] + g_partials[tid + 256];
    sred[tid] = v; __syncthreads();
    for (int s = 128; s > 0; s >>= 1) {
        if (tid < s) sred[tid] += sred[tid + s];
        __syncthreads();
    }
    if (tid == 0) res[0] = sred[0];
    __syncthreads();

    // per-token entropy sum
    sred[tid] = (tid < nTok) ? g_H[tid] : 0.0f; __syncthreads();
    for (int s = 128; s > 0; s >>= 1) {
        if (tid < s) sred[tid] += sred[tid + s];
        __syncthreads();
    }
    if (tid == 0) res[1] = sred[0];
    __syncthreads();

    // commit sq sum
    sred[tid] = (tid < nTok) ? g_sq[tid] : 0.0f; __syncthreads();
    for (int s = 128; s > 0; s >>= 1) {
        if (tid < s) sred[tid] += sred[tid + s];
        __syncthreads();
    }
    if (tid == 0) res[2] = sred[0];
    __syncthreads();

    if (tid == 0) {
        const float entroMean = res[1] / (float)nTok;        // mean over B of (sum/N)
        const float meanEntro = -res[0];
        const float entroLoss = entroMean - meanEntro;       // ALPHA = 1
        const float commit    = res[2] / (float)(nTok * 20);
        out[outBase + 0] = entroMean;
        out[outBase + 1] = meanEntro;
        out[outBase + 2] = entroLoss;
        out[outBase + 3] = commit;
    }
}

extern "C" void kernel_launch(void* const* d_in, const int* in_sizes, int n_in,
                              void* d_out, int out_size)
{
    const float* x = (const float*)d_in[0];
    float* out = (float*)d_out;
    const int nTok = in_sizes[0] / 20;     // 256

    lfq_k1<<<nTok, 256>>>(x, out, nTok);
    dim3 g2(1024 / HT, 4);                 // 128 x 4 = 512 blocks
    lfq_k2<<<g2, 256>>>(nTok);
    lfq_k3<<<1, 256>>>(out, nTok, out_size - 4);
}

// round 7
// speedup vs baseline: 1.8700x; 1.8700x over previous
#include <cuda_runtime.h>
#include <cuda_bf16.h>
#include <math.h>

// TorchLFQ: D=20, K=2^20, TEMP=0.005, tokens = B*N = 256.
// Separable softmax over the +-1 hypercube: l_k = A[k>>10] + B[k&1023].
// K1: per-token fp32 softmax factors pa/pb (1024 each), entropy H, q=sign(x).
// K2: M = pa^T @ pb (1024x1024x256 fp32 GEMM, packed f32x2 FMA),
//     fused sum of (M/T)*log(M/T+1e-10) -> 128 partials.
// K3: fixed-order final reductions -> 4 scalars after q in d_out.
// Deterministic: no atomics, fixed-order reductions, scratch fully rewritten.

#define NTOK 256
#define KT   16

__device__ float g_pa[NTOK * 1024];   // [t][hi]  (token-major, coalesced)
__device__ float g_pb[NTOK * 1024];   // [t][lo]
__device__ float g_H[NTOK];
__device__ float g_sq[NTOK];
__device__ float g_partials[128];

__global__ void __launch_bounds__(256) lfq_k1(const float* __restrict__ x,
                                              float* __restrict__ qout,
                                              int nTok)
{
    const int t    = blockIdx.x;
    const int tid  = threadIdx.x;
    const int lane = tid & 31;
    const int warp = tid >> 5;

    __shared__ float sx[20];
    __shared__ float swr[32];

    if (tid < 20) sx[tid] = x[t * 20 + tid] * 200.0f;   // 1/TEMP = 200
    __syncthreads();

    // logit partial sums for both halves (hi bits -> A, lo bits -> B)
    float vA[4], vB[4];
    #pragma unroll
    for (int r = 0; r < 4; r++) {
        const int h = r * 256 + tid;
        float a = 0.0f, b = 0.0f;
        #pragma unroll
        for (int d = 0; d < 10; d++) {
            const float sa = sx[d], sb = sx[10 + d];
            if ((h >> (9 - d)) & 1) { a += sa; b += sb; }
            else                    { a -= sa; b -= sb; }
        }
        vA[r] = a; vB[r] = b;
    }

    // block max for A and B (warp shuffle + one smem round)
    float mA = fmaxf(fmaxf(vA[0], vA[1]), fmaxf(vA[2], vA[3]));
    float mB = fmaxf(fmaxf(vB[0], vB[1]), fmaxf(vB[2], vB[3]));
    #pragma unroll
    for (int o = 16; o; o >>= 1) {
        mA = fmaxf(mA, __shfl_xor_sync(0xffffffffu, mA, o));
        mB = fmaxf(mB, __shfl_xor_sync(0xffffffffu, mB, o));
    }
    if (lane == 0) { swr[warp] = mA; swr[8 + warp] = mB; }
    __syncthreads();
    float gA = swr[0], gB = swr[8];
    #pragma unroll
    for (int i = 1; i < 8; i++) {
        gA = fmaxf(gA, swr[i]);
        gB = fmaxf(gB, swr[8 + i]);
    }
    __syncthreads();   // before swr reuse

    // exp + Z/S sums
    float eA[4], eB[4];
    float zA = 0.f, sA = 0.f, zB = 0.f, sB = 0.f;
    #pragma unroll
    for (int r = 0; r < 4; r++) {
        const float aa = vA[r] - gA;
        const float bb = vB[r] - gB;
        const float ea = expf(aa);
        const float eb = expf(bb);
        eA[r] = ea; eB[r] = eb;
        zA += ea; sA += ea * aa;
        zB += eb; sB += eb * bb;
    }
    #pragma unroll
    for (int o = 16; o; o >>= 1) {
        zA += __shfl_xor_sync(0xffffffffu, zA, o);
        sA += __shfl_xor_sync(0xffffffffu, sA, o);
        zB += __shfl_xor_sync(0xffffffffu, zB, o);
        sB += __shfl_xor_sync(0xffffffffu, sB, o);
    }
    if (lane == 0) {
        swr[warp] = zA; swr[8 + warp] = sA;
        swr[16 + warp] = zB; swr[24 + warp] = sB;
    }
    __syncthreads();
    float ZA = 0.f, SA = 0.f, ZB = 0.f, SB = 0.f;
    #pragma unroll
    for (int i = 0; i < 8; i++) {
        ZA += swr[i]; SA += swr[8 + i]; ZB += swr[16 + i]; SB += swr[24 + i];
    }

    const float iA = 1.0f / ZA, iB = 1.0f / ZB;
    #pragma unroll
    for (int r = 0; r < 4; r++) {
        g_pa[t * 1024 + r * 256 + tid] = eA[r] * iA;
        g_pb[t * 1024 + r * 256 + tid] = eB[r] * iB;
    }
    if (tid == 0)
        g_H[t] = logf(ZA) - SA / ZA + logf(ZB) - SB / ZB;

    // q = sign(x), commit partial (parallel across first 20 lanes)
    float dd = 0.0f;
    if (tid < 20) {
        const float xv = x[t * 20 + tid];
        const float qv = (xv > 0.0f) ? 1.0f : -1.0f;
        qout[t * 20 + tid] = qv;
        const float d0 = xv - qv;
        dd = d0 * d0;
    }
    if (warp == 0) {
        #pragma unroll
        for (int o = 16; o; o >>= 1) dd += __shfl_xor_sync(0xffffffffu, dd, o);
        if (lane == 0) g_sq[t] = dd;
    }
}

// K2: block tile 128(M) x 64(N), thread tile 8x4, K-tile 16, packed f32x2 FMA.
__global__ void __launch_bounds__(256) lfq_k2(int nTok)
{
    __shared__ float sA[KT][128];      // A tile: [k][row]
    __shared__ float sB[KT][128];      // B tile duplicated pairs: col c -> floats 2c,2c+1
    __shared__ float sred[256];

    const int tid   = threadIdx.x;
    const int tx    = tid & 15;        // col group: cols tx*4 .. tx*4+3
    const int ty    = tid >> 4;        // row group: rows ty*8 .. ty*8+7
    const int iBase = blockIdx.x * 128;
    const int jBase = blockIdx.y * 64;

    unsigned long long acc[4][4];      // [rowpair][col], lanes = (row 2r, row 2r+1)
    #pragma unroll
    for (int r = 0; r < 4; r++)
        #pragma unroll
        for (int c = 0; c < 4; c++) acc[r][c] = 0ull;

    for (int t0 = 0; t0 < nTok; t0 += KT) {
        // A: KT*128 floats = KT*32 float4, 2 per thread, coalesced
        #pragma unroll
        for (int s = 0; s < (KT * 32) / 256; s++) {
            const int idx = tid + s * 256;
            const int row = idx >> 5;
            const int cv  = idx & 31;
            *reinterpret_cast<float4*>(&sA[row][cv * 4]) =
                *reinterpret_cast<const float4*>(&g_pa[(t0 + row) * 1024 + iBase + cv * 4]);
        }
        // B: KT*64 floats = KT*32 float2, duplicated into pairs on store
        #pragma unroll
        for (int s = 0; s < (KT * 32) / 256; s++) {
            const int idx = tid + s * 256;
            const int row = idx >> 5;
            const int cv  = idx & 31;
            const float2 v = *reinterpret_cast<const float2*>(
                &g_pb[(t0 + row) * 1024 + jBase + cv * 2]);
            *reinterpret_cast<float4*>(&sB[row][cv * 4]) =
                make_float4(v.x, v.x, v.y, v.y);
        }
        __syncthreads();

        #pragma unroll
        for (int k = 0; k < KT; k++) {
            const ulonglong2 a01 = *reinterpret_cast<const ulonglong2*>(&sA[k][ty * 8]);
            const ulonglong2 a23 = *reinterpret_cast<const ulonglong2*>(&sA[k][ty * 8 + 4]);
            const ulonglong2 b01 = *reinterpret_cast<const ulonglong2*>(&sB[k][tx * 8]);
            const ulonglong2 b23 = *reinterpret_cast<const ulonglong2*>(&sB[k][tx * 8 + 4]);
            const unsigned long long ap[4] = {a01.x, a01.y, a23.x, a23.y};
            const unsigned long long bp[4] = {b01.x, b01.y, b23.x, b23.y};
            #pragma unroll
            for (int r = 0; r < 4; r++)
                #pragma unroll
                for (int c = 0; c < 4; c++)
                    asm("fma.rn.f32x2 %0, %1, %2, %0;"
                        : "+l"(acc[r][c]) : "l"(ap[r]), "l"(bp[c]));
        }
        __syncthreads();
    }

    // fused mixture-entropy contribution
    const float inv = 1.0f / (float)nTok;
    float local = 0.0f;
    #pragma unroll
    for (int r = 0; r < 4; r++)
        #pragma unroll
        for (int c = 0; c < 4; c++) {
            float2 f;
            f = *reinterpret_cast<const float2*>(&acc[r][c]);
            const float m0 = f.x * inv;
            const float m1 = f.y * inv;
            local += m0 * logf(m0 + 1e-10f) + m1 * logf(m1 + 1e-10f);
        }

    sred[tid] = local; __syncthreads();
    for (int s = 128; s > 0; s >>= 1) {
        if (tid < s) sred[tid] += sred[tid + s];
        __syncthreads();
    }
    if (tid == 0)
        g_partials[blockIdx.x * gridDim.y + blockIdx.y] = sred[0];
}

__global__ void __launch_bounds__(256) lfq_k3(float* __restrict__ out,
                                              int nTok, int outBase)
{
    const int tid = threadIdx.x;
    __shared__ float sred[256];
    __shared__ float res[3];

    // mixture-entropy partials (128 -> 1)
    sred[tid] = (tid < 128) ? g_partials[tid] : 0.0f; __syncthreads();
    for (int s = 128; s > 0; s >>= 1) {
        if (tid < s) sred[tid] += sred[tid + s];
        __syncthreads();
    }
    if (tid == 0) res[0] = sred[0];
    __syncthreads();

    // per-token entropy sum
    sred[tid] = (tid < nTok) ? g_H[tid] : 0.0f; __syncthreads();
    for (int s = 128; s > 0; s >>= 1) {
        if (tid < s) sred[tid] += sred[tid + s];
        __syncthreads();
    }
    if (tid == 0) res[1] = sred[0];
    __syncthreads();

    // commit sq sum
    sred[tid] = (tid < nTok) ? g_sq[tid] : 0.0f; __syncthreads();
    for (int s = 128; s > 0; s >>= 1) {
        if (tid < s) sred[tid] += sred[tid + s];
        __syncthreads();
    }
    if (tid == 0) res[2] = sred[0];
    __syncthreads();

    if (tid == 0) {
        const float entroMean = res[1] / (float)nTok;
        const float meanEntro = -res[0];
        const float entroLoss = entroMean - meanEntro;   // ALPHA = 1
        const float commit    = res[2] / (float)(nTok * 20);
        out[outBase + 0] = entroMean;
        out[outBase + 1] = meanEntro;
        out[outBase + 2] = entroLoss;
        out[outBase + 3] = commit;
    }
}

extern "C" void kernel_launch(void* const* d_in, const int* in_sizes, int n_in,
                              void* d_out, int out_size)
{
    const float* x = (const float*)d_in[0];
    float* out = (float*)d_out;
    const int nTok = in_sizes[0] / 20;     // 256

    lfq_k1<<<nTok, 256>>>(x, out, nTok);
    dim3 g2(8, 16);                        // 1024/128 x 1024/64 = 128 blocks
    lfq_k2<<<g2, 256>>>(nTok);
    lfq_k3<<<1, 256>>>(out, nTok, out_size - 4);
}